// round 2
// baseline (speedup 1.0000x reference)
#include <cuda_runtime.h>

// ---------------- problem constants ----------------
#define C 96                 // feature channels (d = h = 96)
#define NMAX 65536
#define EMAX 1048576

// ---------------- device scratch (no allocations allowed) ----------------
__device__ int   d_is64;               // edge_index dtype flag (1 = int64, 0 = int32)
__device__ int   d_deg[NMAX];
__device__ int   d_rowptr[NMAX + 1];
__device__ int   d_cursor[NMAX];
__device__ int2  d_csr[EMAX];          // (src, norm-weight-as-bits) per edge, binned by dst
__device__ float d_dinv[NMAX];
__device__ float d_h1[(size_t)NMAX * C];    // GEMM output / message buffer
__device__ float d_xgcn[(size_t)NMAX * C];  // first GCN output
__device__ float d_g[(size_t)NMAX * C];     // gate u = r

// ---------------- small helpers ----------------
__device__ __forceinline__ float fsigmoid(float x) {
    return 1.0f / (1.0f + __expf(-x));
}
__device__ __forceinline__ float ftanh(float x) {
    return 1.0f - 2.0f / (__expf(2.0f * x) + 1.0f);
}

// Load edge index entry `idx` (logical element index into a 2E-element array)
// honoring the runtime-detected dtype.
__device__ __forceinline__ int load_idx(const void* ei, int idx, int is64) {
    if (is64) return (int)((const long long*)ei)[idx];
    return ((const int*)ei)[idx];
}

// ---------------- dtype detection ----------------
// If the buffer is int64 (values < 2^31), every odd int32 word is the zero
// high-half. With int32 layout these words are random src indices; the chance
// all ~1024 sampled are zero is negligible.
__global__ void detect_kernel(const int* __restrict__ ei32, int E2) {
    if (threadIdx.x == 0 && blockIdx.x == 0) {
        int nonzero = 0;
        int lim = 2 * E2;          // int32 words available under int32 layout
        if (lim > 2048) lim = 2048;
        for (int i = 1; i < lim; i += 2) nonzero |= ei32[i];
        d_is64 = (nonzero == 0) ? 1 : 0;
    }
}

// ---------------- CSR construction ----------------
__global__ void zero_deg_kernel(int N) {
    int i = blockIdx.x * blockDim.x + threadIdx.x;
    if (i < N) d_deg[i] = 0;
}

__global__ void hist_kernel(const void* __restrict__ ei, int E, int N) {
    int e = blockIdx.x * blockDim.x + threadIdx.x;
    if (e >= E) return;
    int is64 = d_is64;
    int d = load_idx(ei, E + e, is64);
    if ((unsigned)d < (unsigned)N) atomicAdd(&d_deg[d], 1);
}

// Single-block scan: exclusive prefix over edge counts -> rowptr/cursor,
// plus dinv = rsqrt(deg_edges + 1)  (the +1 is the self-loop).
__global__ void scan_kernel(int N) {
    __shared__ int wsum[32];
    const int tid  = threadIdx.x;
    const int lane = tid & 31;
    const int wid  = tid >> 5;
    int carry = 0;
    for (int base = 0; base < N; base += 1024) {
        int i = base + tid;
        int v = (i < N) ? d_deg[i] : 0;
        if (i < N) d_dinv[i] = rsqrtf((float)v + 1.0f);
        int x = v;
        #pragma unroll
        for (int off = 1; off < 32; off <<= 1) {
            int y = __shfl_up_sync(0xffffffffu, x, off);
            if (lane >= off) x += y;
        }
        if (lane == 31) wsum[wid] = x;
        __syncthreads();
        if (wid == 0) {
            int s = wsum[lane];
            #pragma unroll
            for (int off = 1; off < 32; off <<= 1) {
                int y = __shfl_up_sync(0xffffffffu, s, off);
                if (lane >= off) s += y;
            }
            wsum[lane] = s;
        }
        __syncthreads();
        int wprefix = (wid > 0) ? wsum[wid - 1] : 0;
        int incl = x + wprefix;
        int excl = carry + incl - v;
        if (i < N) { d_rowptr[i] = excl; d_cursor[i] = excl; }
        int total = wsum[31];
        __syncthreads();   // protect wsum before next chunk overwrites it
        carry += total;
    }
    if (tid == 0) d_rowptr[N] = carry;
}

__global__ void fill_kernel(const void* __restrict__ ei, int E, int N) {
    int e = blockIdx.x * blockDim.x + threadIdx.x;
    if (e >= E) return;
    int is64 = d_is64;
    int s = load_idx(ei, e, is64);
    int d = load_idx(ei, E + e, is64);
    if ((unsigned)s >= (unsigned)N || (unsigned)d >= (unsigned)N) return;
    int p = atomicAdd(&d_cursor[d], 1);
    d_csr[p] = make_int2(s, __float_as_int(d_dinv[s] * d_dinv[d]));
}

// ---------------- dense GEMM: out[N,96] = A[N,K] @ W[K,96] ----------------
// MODE 0: K=96,  A = A0
// MODE 1: K=192, A = [A0, A1]
// MODE 2: K=192, A = [A0, A1 .* A2]
// Tile: 64 rows x 96 cols, 128 threads, each thread 4 rows x 12 cols.
template <int MODE>
__global__ void __launch_bounds__(128, 4) gemm_kernel(
    const float* __restrict__ A0, const float* __restrict__ A1,
    const float* __restrict__ A2, const float* __restrict__ W,
    float* __restrict__ out, int N)
{
    __shared__ float Ws[C * C];       // one 96-row segment of W
    __shared__ float As[16][64];      // [k][row] staging

    const int tid  = threadIdx.x;
    const int tx   = tid & 7;         // col group: cols tx*12 .. tx*12+11
    const int ty   = tid >> 3;        // row group: rows ty*4 .. ty*4+3
    const int row0 = blockIdx.x * 64;
    const int NSEG = (MODE == 0) ? 1 : 2;

    float acc[4][12];
    #pragma unroll
    for (int r = 0; r < 4; r++)
        #pragma unroll
        for (int c = 0; c < 12; c++) acc[r][c] = 0.0f;

    for (int seg = 0; seg < NSEG; seg++) {
        const float* wseg = W + (size_t)seg * C * C;
        for (int i = tid * 4; i < C * C; i += 128 * 4)
            *(float4*)&Ws[i] = *(const float4*)&wseg[i];
        __syncthreads();

        const float* Asrc = (seg == 0) ? A0 : A1;

        for (int k0 = 0; k0 < C; k0 += 16) {
            {
                int r   = tid >> 1;
                int kq  = (tid & 1) * 8;
                int row = row0 + r;
                float4 v0, v1;
                if (row < N) {
                    const float* base = Asrc + (size_t)row * C + k0 + kq;
                    v0 = *(const float4*)(base);
                    v1 = *(const float4*)(base + 4);
                    if (MODE == 2 && seg == 1) {
                        const float* gb = A2 + (size_t)row * C + k0 + kq;
                        float4 g0 = *(const float4*)(gb);
                        float4 g1 = *(const float4*)(gb + 4);
                        v0.x *= g0.x; v0.y *= g0.y; v0.z *= g0.z; v0.w *= g0.w;
                        v1.x *= g1.x; v1.y *= g1.y; v1.z *= g1.z; v1.w *= g1.w;
                    }
                } else {
                    v0 = make_float4(0.f, 0.f, 0.f, 0.f);
                    v1 = v0;
                }
                As[kq + 0][r] = v0.x; As[kq + 1][r] = v0.y;
                As[kq + 2][r] = v0.z; As[kq + 3][r] = v0.w;
                As[kq + 4][r] = v1.x; As[kq + 5][r] = v1.y;
                As[kq + 6][r] = v1.z; As[kq + 7][r] = v1.w;
            }
            __syncthreads();

            #pragma unroll
            for (int kk = 0; kk < 16; kk++) {
                float4 av = *(const float4*)&As[kk][ty * 4];
                const float* wr = &Ws[(k0 + kk) * C + tx * 12];
                float4 w0 = *(const float4*)(wr);
                float4 w1 = *(const float4*)(wr + 4);
                float4 w2 = *(const float4*)(wr + 8);
                float a[4]  = {av.x, av.y, av.z, av.w};
                float w[12] = {w0.x, w0.y, w0.z, w0.w,
                               w1.x, w1.y, w1.z, w1.w,
                               w2.x, w2.y, w2.z, w2.w};
                #pragma unroll
                for (int r = 0; r < 4; r++)
                    #pragma unroll
                    for (int c = 0; c < 12; c++)
                        acc[r][c] += a[r] * w[c];
            }
            __syncthreads();
        }
    }

    #pragma unroll
    for (int r = 0; r < 4; r++) {
        int row = row0 + ty * 4 + r;
        if (row < N) {
            float* o = out + (size_t)row * C + tx * 12;
            *(float4*)(o)     = make_float4(acc[r][0], acc[r][1], acc[r][2],  acc[r][3]);
            *(float4*)(o + 4) = make_float4(acc[r][4], acc[r][5], acc[r][6],  acc[r][7]);
            *(float4*)(o + 8) = make_float4(acc[r][8], acc[r][9], acc[r][10], acc[r][11]);
        }
    }
}

// ---------------- CSR gather aggregation ----------------
// One warp per node; lane owns channels {lane, lane+32, lane+64}.
// out[n] = bias + dinv[n]^2 * H[n] + sum_{(s,w) in CSR bin n} w * H[s]
// MODE 0: store raw           (x_gcn)
// MODE 1: store sigmoid       (gate g)
// MODE 2: c=tanh(.), out = g*h_prev + (1-g)*c   (final GRU output)
template <int MODE>
__global__ void agg_kernel(const float* __restrict__ H,
                           const float* __restrict__ bias,
                           const float* __restrict__ G,
                           const float* __restrict__ HP,
                           float* __restrict__ out, int N)
{
    int gw   = (blockIdx.x * blockDim.x + threadIdx.x) >> 5;
    int lane = threadIdx.x & 31;
    if (gw >= N) return;
    const int n = gw;

    const int c0 = lane, c1 = lane + 32, c2 = lane + 64;
    float dn = d_dinv[n];
    float sw = dn * dn;
    const float* hn = H + (size_t)n * C;
    float a0 = bias[c0] + sw * hn[c0];
    float a1 = bias[c1] + sw * hn[c1];
    float a2 = bias[c2] + sw * hn[c2];

    int j   = d_rowptr[n];
    int end = d_rowptr[n + 1];
    int2 p  = (j < end) ? d_csr[j] : make_int2(0, 0);
    for (; j < end; j++) {
        int2 pn = (j + 1 < end) ? d_csr[j + 1] : p;   // prefetch next edge
        const float* hs = H + (size_t)p.x * C;
        float w = __int_as_float(p.y);
        a0 += w * hs[c0];
        a1 += w * hs[c1];
        a2 += w * hs[c2];
        p = pn;
    }

    size_t o = (size_t)n * C;
    if (MODE == 0) {
        out[o + c0] = a0; out[o + c1] = a1; out[o + c2] = a2;
    } else if (MODE == 1) {
        out[o + c0] = fsigmoid(a0);
        out[o + c1] = fsigmoid(a1);
        out[o + c2] = fsigmoid(a2);
    } else {
        float u0 = G[o + c0], u1 = G[o + c1], u2 = G[o + c2];
        float p0 = HP[o + c0], p1 = HP[o + c1], p2 = HP[o + c2];
        out[o + c0] = u0 * p0 + (1.0f - u0) * ftanh(a0);
        out[o + c1] = u1 * p1 + (1.0f - u1) * ftanh(a1);
        out[o + c2] = u2 * p2 + (1.0f - u2) * ftanh(a2);
    }
}

// ---------------- launch ----------------
extern "C" void kernel_launch(void* const* d_in, const int* in_sizes, int n_in,
                              void* d_out, int out_size)
{
    const float* x      = (const float*)d_in[0];
    const void*  ei     = d_in[1];
    const float* h_prev = (const float*)d_in[2];
    const float* Wx     = (const float*)d_in[3];
    const float* bx     = (const float*)d_in[4];
    const float* Wuh    = (const float*)d_in[5];
    const float* buh    = (const float*)d_in[6];
    const float* Wch    = (const float*)d_in[7];
    const float* bch    = (const float*)d_in[8];
    float*       out    = (float*)d_out;

    int N = in_sizes[0] / C;
    int E = in_sizes[1] / 2;
    if (N > NMAX) N = NMAX;
    if (E > EMAX) E = EMAX;

    const int TB = 256;
    int nb_nodes = (N + TB - 1) / TB;
    int nb_edges = (E + TB - 1) / TB;
    int nb_gemm  = (N + 63) / 64;
    int nb_agg   = (N * 32 + TB - 1) / TB;

    // CSR + normalization (deg also yields dinv)
    detect_kernel<<<1, 32>>>((const int*)ei, E);
    zero_deg_kernel<<<nb_nodes, TB>>>(N);
    hist_kernel<<<nb_edges, TB>>>(ei, E, N);
    scan_kernel<<<1, 1024>>>(N);
    fill_kernel<<<nb_edges, TB>>>(ei, E, N);

    // GCN 1: h1 = x @ Wx ; x_gcn = S h1 + bx
    gemm_kernel<0><<<nb_gemm, 128>>>(x, nullptr, nullptr, Wx, d_h1, N);
    agg_kernel<0><<<nb_agg, TB>>>(d_h1, bx, nullptr, nullptr, d_xgcn, N);

    // GCN 2: h1 = [x_gcn, h_prev] @ Wuh ; g = sigmoid(S h1 + buh)
    gemm_kernel<1><<<nb_gemm, 128>>>(d_xgcn, h_prev, nullptr, Wuh, d_h1, N);
    agg_kernel<1><<<nb_agg, TB>>>(d_h1, buh, nullptr, nullptr, d_g, N);

    // GCN 3: h1 = [x_gcn, g .* h_prev] @ Wch ; c = tanh(S h1 + bch)
    // out = g*h_prev + (1-g)*c
    gemm_kernel<2><<<nb_gemm, 128>>>(d_xgcn, h_prev, d_g, Wch, d_h1, N);
    agg_kernel<2><<<nb_agg, TB>>>(d_h1, bch, d_g, h_prev, out, N);
}